// round 9
// baseline (speedup 1.0000x reference)
#include <cuda_runtime.h>
#include <cuda_fp16.h>
#include <mma.h>
#include <math.h>

#define Bb 4
#define Tt 1024
#define Dd 1024
#define Hh 16
#define HDh 64
#define LR 64
#define BT (Bb*Tt)             /* 4096 */
#define BTD ((long)BT*Dd)      /* 4194304 */
#define STATE (Bb*Hh*HDh*HDh)  /* 262144 */

// ---------------- scratch (device globals; no allocation allowed) ----------
__device__ float  g_dx[BTD];
__device__ __half g_lerpx[BTD];
__device__ __half g_in[5*BTD];
__device__ __half g_t1[(long)BT*384];
__device__ float  g_s1p[2ll*BT*384];   // split-K partials for stage1
__device__ __half g_t2[(long)BT*128];
__device__ __half g_laP[384*1024];
__device__ __half g_lbP[5*1024*64];
__device__ float  g_llP[5*1024];
__device__ __half g_W5[5ll*1024*1024];
__device__ float  g_w[BTD];
__device__ float  g_proj[4*BTD];
__device__ float  g_y[BTD];
__device__ __half g_opre[BTD];
__device__ float  g_stfb[STATE];

__device__ __forceinline__ uint2 h4pack(float a, float b, float c, float d) {
    __half2 p0 = __floats2half2_rn(a, b);
    __half2 p1 = __floats2half2_rn(c, d);
    uint2 r;
    r.x = *reinterpret_cast<unsigned*>(&p0);
    r.y = *reinterpret_cast<unsigned*>(&p1);
    return r;
}

// ---------------- elementwise / pack kernels -------------------------------

__global__ void __launch_bounds__(256) premix_kernel(
        const float* __restrict__ x, const float* __restrict__ xw,
        float* __restrict__ dx, __half* __restrict__ lerpx) {
    long idx = (long)blockIdx.x * 256 + threadIdx.x;
    int dd = (int)(idx % Dd);
    long bt = idx / Dd;
    int t = (int)(bt % Tt);
    float xv = x[idx];
    float xp = (t > 0) ? x[idx - Dd] : 0.f;
    float d = xp - xv;
    dx[idx] = d;
    lerpx[idx] = __float2half_rn(fmaf(d, xw[dd], xv));
}

__global__ void __launch_bounds__(256) pack_la_kernel(
        const float* __restrict__ a0, const float* __restrict__ a1,
        const float* __restrict__ a2, const float* __restrict__ a3,
        const float* __restrict__ a4, __half* __restrict__ dst) {
    long i = (long)blockIdx.x * 256 + threadIdx.x;
    int row = (int)(i >> 10);
    int col = (int)(i & 1023);
    int p = row >> 6;
    float v = 0.f;
    if (p < 5) {
        const float* src = (p == 0) ? a0 : (p == 1) ? a1 : (p == 2) ? a2
                         : (p == 3) ? a3 : a4;
        v = src[(long)(row & 63) * 1024 + col];
    }
    dst[i] = __float2half_rn(v);
}

__global__ void __launch_bounds__(256) pack_lb_kernel(
        const float* __restrict__ b0, const float* __restrict__ b1,
        const float* __restrict__ b2, const float* __restrict__ b3,
        const float* __restrict__ b4, __half* __restrict__ dstb,
        const float* __restrict__ l0, const float* __restrict__ l1,
        const float* __restrict__ l2, const float* __restrict__ l3,
        const float* __restrict__ l4, float* __restrict__ dstl) {
    long i = (long)blockIdx.x * 256 + threadIdx.x;   // 5*1024*64 + 5*1024
    if (i < 5ll * 1024 * 64) {
        int p = (int)(i >> 16);
        long r = i & 65535;
        const float* src = (p == 0) ? b0 : (p == 1) ? b1 : (p == 2) ? b2
                         : (p == 3) ? b3 : b4;
        dstb[i] = __float2half_rn(src[r]);
    } else {
        int j = (int)(i - 5ll * 1024 * 64);
        int p = j >> 10;
        int r = j & 1023;
        const float* src = (p == 0) ? l0 : (p == 1) ? l1 : (p == 2) ? l2
                         : (p == 3) ? l3 : l4;
        dstl[j] = src[r];
    }
}

__global__ void __launch_bounds__(256) pack_w_kernel(
        const float* __restrict__ w0, const float* __restrict__ w1,
        const float* __restrict__ w2, const float* __restrict__ w3,
        const float* __restrict__ w4, __half* __restrict__ dst) {
    long i = (long)blockIdx.x * 256 + threadIdx.x;
    int p = (int)(i >> 20);
    long r = i & 1048575;
    const float* src = (p == 0) ? w0 : (p == 1) ? w1 : (p == 2) ? w2
                     : (p == 3) ? w3 : w4;
    dst[i] = __float2half_rn(src[r]);
}

// t1 = half(tanh(p0 + p1))   (combine split-K partials)
__global__ void __launch_bounds__(256) combine_t1_kernel(
        const float* __restrict__ p, __half* __restrict__ dst) {
    long i = ((long)blockIdx.x * 256 + threadIdx.x) * 4;   // < 4096*384
    float4 a = *(const float4*)&p[i];
    float4 b = *(const float4*)&p[(long)BT * 384 + i];
    uint2 o = h4pack(tanhf(a.x + b.x), tanhf(a.y + b.y),
                     tanhf(a.z + b.z), tanhf(a.w + b.w));
    *(uint2*)&dst[i] = o;
}

// ---------------- fp16 tensor-core GEMM with fused epilogues ---------------
// tile C[128,128] = A[M,K] @ W[N,K]^T  (fp16 operands, fp32 accumulate)
// 4-stage cp.async pipeline, BKK=32.
// MODE 0: Cf = acc                    (float out)
// MODE 1: Ch = half(tanh(acc))        (half out)
// MODE 2: Ch = half(x + dx*(acc+L))   (half out; x/dx row length 1024)
// MODE 3: Cf = exp(-exp(acc+L))       (float out)
#define BKK 32
#define SLDH 40
#define ATILEB (128*SLDH*2)           /* bytes per A (or B) tile: 10240 */
#define STGB (2*ATILEB)               /* bytes per stage: 20480 */
#define GSMEM (4*STGB)                /* 81920 */

template<int MODE>
__global__ void __launch_bounds__(256) gemm_h(
        const __half* __restrict__ A, long sAz, int lda,
        const __half* __restrict__ W, long sWz, int ldw,
        void* __restrict__ Cv, long sCz, int ldc,
        const float* __restrict__ L, long sLz,
        const float* __restrict__ x, const float* __restrict__ dx,
        int K) {
    using namespace nvcuda;
    extern __shared__ __half sm[];
    const int tid = threadIdx.x;
    const int z = blockIdx.z;
    A += (long)z * sAz;
    W += (long)z * sWz;
    if (MODE >= 2) L += (long)z * sLz;
    float* Cf = (float*)Cv + (long)z * sCz;
    __half* Ch = (__half*)Cv + (long)z * sCz;
    const int bm = blockIdx.y * 128;
    const int bn = blockIdx.x * 128;
    const int r2 = tid >> 1;            // 0..127 (row)
    const int q2 = (tid & 1) * 16;      // half offset 0/16; thread covers q2..q2+15
    const __half* aP = A + (long)(bm + r2) * lda + q2;
    const __half* wP = W + (long)(bn + r2) * ldw + q2;
    unsigned dA = (unsigned)__cvta_generic_to_shared(sm) + (r2 * SLDH + q2) * 2;
    const int wid = tid >> 5;
    const int wy = wid >> 1;
    const int wx = wid & 1;

    wmma::fragment<wmma::accumulator, 16, 16, 16, float> acc[2][4];
    #pragma unroll
    for (int i = 0; i < 2; i++)
        #pragma unroll
        for (int j = 0; j < 4; j++)
            wmma::fill_fragment(acc[i][j], 0.0f);

// each thread: 2x16B for A (halves q2..q2+7, q2+8..q2+15) and same for B
#define ISSUE(st, kb) do {                                                   \
        unsigned _a = dA + (st) * STGB;                                      \
        const __half* _ap = aP + (kb) * BKK;                                 \
        const __half* _bp = wP + (kb) * BKK;                                 \
        asm volatile("cp.async.cg.shared.global [%0], [%1], 16;\n" ::       \
            "r"(_a), "l"(_ap));                                              \
        asm volatile("cp.async.cg.shared.global [%0], [%1], 16;\n" ::       \
            "r"(_a + 16), "l"(_ap + 8));                                     \
        asm volatile("cp.async.cg.shared.global [%0], [%1], 16;\n" ::       \
            "r"(_a + ATILEB), "l"(_bp));                                     \
        asm volatile("cp.async.cg.shared.global [%0], [%1], 16;\n" ::       \
            "r"(_a + ATILEB + 16), "l"(_bp + 8));                            \
        asm volatile("cp.async.commit_group;\n");                            \
    } while (0)

    const int nIter = K / BKK;
    #pragma unroll
    for (int i = 0; i < 3; i++)
        if (i < nIter) ISSUE(i, i);

    for (int it = 0; it < nIter; it++) {
        if (it + 3 < nIter) ISSUE((it + 3) & 3, it + 3);
        int ahead = nIter - 1 - it;
        if (ahead > 3) ahead = 3;
        if (ahead == 3)      asm volatile("cp.async.wait_group 3;\n");
        else if (ahead == 2) asm volatile("cp.async.wait_group 2;\n");
        else if (ahead == 1) asm volatile("cp.async.wait_group 1;\n");
        else                 asm volatile("cp.async.wait_group 0;\n");
        __syncthreads();
        const __half* sA = sm + (it & 3) * (STGB / 2);
        const __half* sB = sA + ATILEB / 2;
        #pragma unroll
        for (int kk = 0; kk < BKK; kk += 16) {
            wmma::fragment<wmma::matrix_a, 16, 16, 16, __half, wmma::row_major> af[2];
            wmma::fragment<wmma::matrix_b, 16, 16, 16, __half, wmma::col_major> bf[4];
            #pragma unroll
            for (int i = 0; i < 2; i++)
                wmma::load_matrix_sync(af[i], sA + (wy * 32 + i * 16) * SLDH + kk, SLDH);
            #pragma unroll
            for (int j = 0; j < 4; j++)
                wmma::load_matrix_sync(bf[j], sB + (wx * 64 + j * 16) * SLDH + kk, SLDH);
            #pragma unroll
            for (int i = 0; i < 2; i++)
                #pragma unroll
                for (int j = 0; j < 4; j++)
                    wmma::mma_sync(acc[i][j], af[i], bf[j], acc[i][j]);
        }
        __syncthreads();
    }
#undef ISSUE

    if (MODE == 0) {
        #pragma unroll
        for (int i = 0; i < 2; i++)
            #pragma unroll
            for (int j = 0; j < 4; j++)
                wmma::store_matrix_sync(
                    Cf + (long)(bm + wy * 32 + i * 16) * ldc + bn + wx * 64 + j * 16,
                    acc[i][j], ldc, wmma::mem_row_major);
    } else {
        float* smf = reinterpret_cast<float*>(sm);
        #pragma unroll
        for (int i = 0; i < 2; i++)
            #pragma unroll
            for (int j = 0; j < 4; j++)
                wmma::store_matrix_sync(
                    smf + (wy * 32 + i * 16) * 128 + wx * 64 + j * 16,
                    acc[i][j], 128, wmma::mem_row_major);
        __syncthreads();
        int row = tid >> 1;
        int c0 = (tid & 1) * 64;
        long gro = bm + row;
        #pragma unroll
        for (int i = 0; i < 16; i++) {
            int c = c0 + i * 4;
            float4 m = *(float4*)&smf[row * 128 + c];
            if (MODE == 1) {
                uint2 o = h4pack(tanhf(m.x), tanhf(m.y), tanhf(m.z), tanhf(m.w));
                *(uint2*)&Ch[gro * ldc + bn + c] = o;
            } else if (MODE == 2) {
                float4 lv = *(const float4*)&L[bn + c];
                long gi = gro * 1024 + bn + c;
                float4 xv = *(const float4*)&x[gi];
                float4 dv = *(const float4*)&dx[gi];
                uint2 o = h4pack(fmaf(dv.x, m.x + lv.x, xv.x),
                                 fmaf(dv.y, m.y + lv.y, xv.y),
                                 fmaf(dv.z, m.z + lv.z, xv.z),
                                 fmaf(dv.w, m.w + lv.w, xv.w));
                *(uint2*)&Ch[gro * ldc + bn + c] = o;
            } else {
                float4 lv = *(const float4*)&L[bn + c];
                float4 o;
                o.x = expf(-expf(m.x + lv.x));
                o.y = expf(-expf(m.y + lv.y));
                o.z = expf(-expf(m.z + lv.z));
                o.w = expf(-expf(m.w + lv.w));
                *(float4*)&Cf[gro * ldc + bn + c] = o;
            }
        }
    }
}

// ---------------- recurrent scan: 128 CTAs (column split) ------------------
__global__ void __launch_bounds__(256) scan2_kernel(
        const float* __restrict__ r, const float* __restrict__ w,
        const float* __restrict__ k, const float* __restrict__ v,
        const float* __restrict__ init_state, const float* __restrict__ u,
        float* __restrict__ y, float* __restrict__ state_out) {
    int cta = blockIdx.x;
    int bh = cta >> 1, jh = cta & 1;
    int b = bh / Hh, h = bh % Hh;
    int tid = threadIdx.x;
    int j32 = tid & 31;
    int gi = tid >> 5;
    int j = jh * 32 + j32;
    __shared__ float shr[64], shw[64], shk[64], shv[32];
    __shared__ float ypart[2][8][32];
    float S[8], uu[8];
    #pragma unroll
    for (int ii = 0; ii < 8; ii++) {
        int i = gi * 8 + ii;
        S[ii] = init_state[(long)(h * 64 + i) * 64 + j];
        uu[ii] = u[h * 64 + i];
    }
    long base = (long)b * Tt * Dd + (long)h * 64;
    const float* myp = nullptr;
    float* slot = nullptr;
    if (tid < 64)       { myp = r + base + tid;               slot = &shr[tid]; }
    else if (tid < 128) { myp = w + base + (tid - 64);        slot = &shw[tid - 64]; }
    else if (tid < 192) { myp = k + base + (tid - 128);       slot = &shk[tid - 128]; }
    else if (tid < 224) { myp = v + base + jh * 32 + (tid - 192); slot = &shv[tid - 192]; }
    float pref = myp ? myp[0] : 0.f;
    for (int t = 0; t < Tt; t++) {
        if (slot) *slot = pref;
        __syncthreads();
        if (myp && t + 1 < Tt) pref = myp[(long)(t + 1) * Dd];
        float vj = shv[j32];
        float acc = 0.f;
        #pragma unroll
        for (int ii = 0; ii < 8; ii++) {
            int i = gi * 8 + ii;
            float kv = shk[i] * vj;
            acc = fmaf(shr[i], fmaf(uu[ii], kv, S[ii]), acc);
            S[ii] = fmaf(shw[i], S[ii], kv);
        }
        ypart[t & 1][gi][j32] = acc;
        __syncthreads();
        if (gi == 0) {
            float yy = 0.f;
            #pragma unroll
            for (int g2 = 0; g2 < 8; g2++) yy += ypart[t & 1][g2][j32];
            y[base + (long)t * Dd + j] = yy;
        }
    }
    #pragma unroll
    for (int ii = 0; ii < 8; ii++) {
        int i = gi * 8 + ii;
        state_out[(long)((b * Hh + h) * 64 + i) * 64 + j] = S[ii];
    }
}

// ---------------- groupnorm + silu gate ------------------------------------
__global__ void __launch_bounds__(256) gn_gate_kernel(
        const float* __restrict__ y, const float* __restrict__ g,
        const float* __restrict__ lnw, const float* __restrict__ lnb,
        __half* __restrict__ out) {
    long warp = ((long)blockIdx.x * blockDim.x + threadIdx.x) >> 5;
    int lane = threadIdx.x & 31;
    if (warp >= (long)Bb * Tt * Hh) return;
    const float* yp = y + warp * 64;
    float v0 = yp[lane], v1 = yp[lane + 32];
    float s = v0 + v1;
    #pragma unroll
    for (int off = 16; off > 0; off >>= 1) s += __shfl_xor_sync(0xffffffffu, s, off);
    float mean = s * (1.f / 64.f);
    float d0 = v0 - mean, d1 = v1 - mean;
    float vs = d0 * d0 + d1 * d1;
    #pragma unroll
    for (int off = 16; off > 0; off >>= 1) vs += __shfl_xor_sync(0xffffffffu, vs, off);
    float inv = rsqrtf(vs * (1.f / 64.f) + 1e-5f);
    float n0 = fmaf(d0 * inv, lnw[lane], lnb[lane]);
    float n1 = fmaf(d1 * inv, lnw[lane + 32], lnb[lane + 32]);
    float g0 = g[warp * 64 + lane];
    float g1 = g[warp * 64 + lane + 32];
    float s0 = g0 / (1.f + expf(-g0));
    float s1 = g1 / (1.f + expf(-g1));
    out[warp * 64 + lane] = __float2half_rn(s0 * n0);
    out[warp * 64 + lane + 32] = __float2half_rn(s1 * n1);
}

// ---------------- host -----------------------------------------------------
static void* symaddr(const void* s) {
    void* p = nullptr;
    cudaGetSymbolAddress(&p, s);
    return p;
}

extern "C" void kernel_launch(void* const* d_in, const int* in_sizes, int n_in,
                              void* d_out, int out_size) {
    (void)in_sizes; (void)n_in;
    const float* x    = (const float*)d_in[0];
    const float* xw   = (const float*)d_in[1];
    const float* rW   = (const float*)d_in[2];
    const float* kW   = (const float*)d_in[3];
    const float* vW   = (const float*)d_in[4];
    const float* gW   = (const float*)d_in[5];
    const float* la[5] = {(const float*)d_in[6],  (const float*)d_in[9],
                          (const float*)d_in[12], (const float*)d_in[15],
                          (const float*)d_in[18]};
    const float* lb[5] = {(const float*)d_in[7],  (const float*)d_in[10],
                          (const float*)d_in[13], (const float*)d_in[16],
                          (const float*)d_in[19]};
    const float* ll[5] = {(const float*)d_in[8],  (const float*)d_in[11],
                          (const float*)d_in[14], (const float*)d_in[17],
                          (const float*)d_in[20]};
    const float* ln_w = (const float*)d_in[21];
    const float* ln_b = (const float*)d_in[22];
    const float* oW   = (const float*)d_in[23];
    const float* init_state = (const float*)d_in[24];
    const float* u    = (const float*)d_in[25];

    float* out = (float*)d_out;

    float*  p_dx    = (float*)symaddr(g_dx);
    __half* p_lerpx = (__half*)symaddr(g_lerpx);
    __half* p_in    = (__half*)symaddr(g_in);
    __half* p_t1    = (__half*)symaddr(g_t1);
    float*  p_s1p   = (float*)symaddr(g_s1p);
    __half* p_t2    = (__half*)symaddr(g_t2);
    __half* p_laP   = (__half*)symaddr(g_laP);
    __half* p_lbP   = (__half*)symaddr(g_lbP);
    float*  p_llP   = (float*)symaddr(g_llP);
    __half* p_W5    = (__half*)symaddr(g_W5);
    float*  p_w     = (float*)symaddr(g_w);
    float*  p_proj  = (float*)symaddr(g_proj);
    float*  p_y     = (float*)symaddr(g_y);
    __half* p_opre  = (__half*)symaddr(g_opre);
    float*  p_stfb  = (float*)symaddr(g_stfb);

    static cudaStream_t sA = nullptr, sB = nullptr;
    static cudaEvent_t eF = nullptr, eW = nullptr, eL = nullptr,
                       eWG = nullptr, eP = nullptr, eG = nullptr, eB = nullptr;
    if (!sA) {
        cudaStreamCreateWithFlags(&sA, cudaStreamNonBlocking);
        cudaStreamCreateWithFlags(&sB, cudaStreamNonBlocking);
        cudaEventCreateWithFlags(&eF, cudaEventDisableTiming);
        cudaEventCreateWithFlags(&eW, cudaEventDisableTiming);
        cudaEventCreateWithFlags(&eL, cudaEventDisableTiming);
        cudaEventCreateWithFlags(&eWG, cudaEventDisableTiming);
        cudaEventCreateWithFlags(&eP, cudaEventDisableTiming);
        cudaEventCreateWithFlags(&eG, cudaEventDisableTiming);
        cudaEventCreateWithFlags(&eB, cudaEventDisableTiming);
        cudaFuncSetAttribute(gemm_h<0>, cudaFuncAttributeMaxDynamicSharedMemorySize, GSMEM);
        cudaFuncSetAttribute(gemm_h<1>, cudaFuncAttributeMaxDynamicSharedMemorySize, GSMEM);
        cudaFuncSetAttribute(gemm_h<2>, cudaFuncAttributeMaxDynamicSharedMemorySize, GSMEM);
        cudaFuncSetAttribute(gemm_h<3>, cudaFuncAttributeMaxDynamicSharedMemorySize, GSMEM);
    }

    // ---- forks: packs run off the critical path
    cudaEventRecord(eF, 0);
    cudaStreamWaitEvent(sA, eF, 0);
    pack_w_kernel<<<(5 * 1024 * 1024) / 256, 256, 0, sA>>>(rW, kW, vW, gW, oW, p_W5);
    cudaEventRecord(eW, sA);
    cudaStreamWaitEvent(sB, eF, 0);
    pack_la_kernel<<<(384 * 1024) / 256, 256, 0, sB>>>(la[0], la[1], la[2], la[3], la[4], p_laP);
    pack_lb_kernel<<<(5 * 1024 * 64 + 5 * 1024 + 255) / 256, 256, 0, sB>>>(
        lb[0], lb[1], lb[2], lb[3], lb[4], p_lbP,
        ll[0], ll[1], ll[2], ll[3], ll[4], p_llP);
    cudaEventRecord(eB, sB);

    // ---- main chain
    premix_kernel<<<(int)(BTD / 256), 256>>>(x, xw, p_dx, p_lerpx);

    // lora stage 1, split-K z=2: s1p[z] = lerpx[:, z*512:] @ laP[:, z*512:]^T
    cudaStreamWaitEvent(0, eB, 0);
    gemm_h<0><<<dim3(3, 32, 2), 256, GSMEM>>>(
        p_lerpx, 512, 1024, p_laP, 512, 1024, p_s1p, (long)BT * 384, 384,
        nullptr, 0, nullptr, nullptr, 512);
    combine_t1_kernel<<<(BT * 384) / 1024, 256>>>(p_s1p, p_t1);

    // fused lora stage 2 + mix, all 5 paths
    gemm_h<2><<<dim3(8, 32, 5), 256, GSMEM>>>(
        p_t1, 64, 384, p_lbP, 65536, 64, p_in, BTD, 1024,
        p_llP, 1024, x, p_dx, 64);

    // ---- fork: d-lora second pass (t2, w) on sA, parallel with projections
    cudaEventRecord(eL, 0);
    cudaStreamWaitEvent(sA, eL, 0);
    gemm_h<1><<<dim3(1, 32, 1), 256, GSMEM, sA>>>(
        p_in + 4 * BTD, 0, 1024, p_laP + 256 * 1024, 0, 1024, p_t2, 0, 128,
        nullptr, 0, nullptr, nullptr, 1024);
    gemm_h<3><<<dim3(8, 32, 1), 256, GSMEM, sA>>>(
        p_t2, 0, 128, p_lbP + 4 * 65536, 0, 64, p_w, 0, 1024,
        p_llP + 4 * 1024, 0, nullptr, nullptr, 64);
    cudaEventRecord(eWG, sA);

    // ---- r,k,v projections (need packed weights)
    cudaStreamWaitEvent(0, eW, 0);
    gemm_h<0><<<dim3(8, 32, 3), 256, GSMEM>>>(
        p_in, BTD, 1024, p_W5, 1024 * 1024, 1024, p_proj, BTD, 1024,
        nullptr, 0, nullptr, nullptr, 1024);

    // ---- fork: g projection on sB, parallel with the scan
    cudaEventRecord(eP, 0);
    cudaStreamWaitEvent(sB, eP, 0);
    gemm_h<0><<<dim3(8, 32, 1), 256, GSMEM, sB>>>(
        p_in + 3 * BTD, 0, 1024, p_W5 + 3ll * 1024 * 1024, 0, 1024,
        p_proj + 3 * BTD, 0, 1024, nullptr, 0, nullptr, nullptr, 1024);
    cudaEventRecord(eG, sB);

    // ---- recurrent scan (needs r,k,v + w)
    cudaStreamWaitEvent(0, eWG, 0);
    float* st_out = (out_size >= (int)(BTD + STATE)) ? (out + BTD) : p_stfb;
    scan2_kernel<<<2 * Bb * Hh, 256>>>(p_proj, p_w, p_proj + BTD, p_proj + 2 * BTD,
                                       init_state, u, p_y, st_out);

    // ---- gate (needs g) + output projection
    cudaStreamWaitEvent(0, eG, 0);
    gn_gate_kernel<<<(Bb * Tt * Hh) / 8, 256>>>(p_y, p_proj + 3 * BTD, ln_w, ln_b, p_opre);
    gemm_h<0><<<dim3(8, 32, 1), 256, GSMEM>>>(
        p_opre, 0, 1024, p_W5 + 4ll * 1024 * 1024, 0, 1024, out, 0, 1024,
        nullptr, 0, nullptr, nullptr, 1024);
}

// round 10
// speedup vs baseline: 1.0665x; 1.0665x over previous
#include <cuda_runtime.h>
#include <cuda_fp16.h>
#include <mma.h>
#include <math.h>

#define Bb 4
#define Tt 1024
#define Dd 1024
#define Hh 16
#define HDh 64
#define LR 64
#define BT (Bb*Tt)             /* 4096 */
#define BTD ((long)BT*Dd)      /* 4194304 */
#define STATE (Bb*Hh*HDh*HDh)  /* 262144 */

// ---------------- scratch (device globals; no allocation allowed) ----------
__device__ float  g_dx[BTD];
__device__ __half g_lerpx[BTD];
__device__ __half g_in[5*BTD];
__device__ __half g_t1[(long)BT*384];
__device__ float  g_s1p[2ll*BT*384];   // split-K partials for stage1
__device__ __half g_t2[(long)BT*128];
__device__ __half g_laP[384*1024];
__device__ __half g_lbP[5*1024*64];
__device__ float  g_llP[5*1024];
__device__ __half g_W5[5ll*1024*1024];
__device__ float  g_w[BTD];
__device__ float  g_proj[4*BTD];
__device__ float  g_y[BTD];
__device__ __half g_opre[BTD];
__device__ float  g_stfb[STATE];

__device__ __forceinline__ uint2 h4pack(float a, float b, float c, float d) {
    __half2 p0 = __floats2half2_rn(a, b);
    __half2 p1 = __floats2half2_rn(c, d);
    uint2 r;
    r.x = *reinterpret_cast<unsigned*>(&p0);
    r.y = *reinterpret_cast<unsigned*>(&p1);
    return r;
}

// ---------------- elementwise / pack kernels -------------------------------

// vectorized: 4 elements per thread
__global__ void __launch_bounds__(256) premix_kernel(
        const float* __restrict__ x, const float* __restrict__ xw,
        float* __restrict__ dx, __half* __restrict__ lerpx) {
    long idx = ((long)blockIdx.x * 256 + threadIdx.x) * 4;
    int dd = (int)(idx % Dd);
    long bt = idx / Dd;
    int t = (int)(bt % Tt);
    float4 xv = *(const float4*)&x[idx];
    float4 xp = make_float4(0.f, 0.f, 0.f, 0.f);
    if (t > 0) xp = *(const float4*)&x[idx - Dd];
    float4 wv = *(const float4*)&xw[dd];
    float4 d;
    d.x = xp.x - xv.x; d.y = xp.y - xv.y;
    d.z = xp.z - xv.z; d.w = xp.w - xv.w;
    *(float4*)&dx[idx] = d;
    uint2 o = h4pack(fmaf(d.x, wv.x, xv.x), fmaf(d.y, wv.y, xv.y),
                     fmaf(d.z, wv.z, xv.z), fmaf(d.w, wv.w, xv.w));
    *(uint2*)&lerpx[idx] = o;
}

__global__ void __launch_bounds__(256) pack_la_kernel(
        const float* __restrict__ a0, const float* __restrict__ a1,
        const float* __restrict__ a2, const float* __restrict__ a3,
        const float* __restrict__ a4, __half* __restrict__ dst) {
    long i = (long)blockIdx.x * 256 + threadIdx.x;
    int row = (int)(i >> 10);
    int col = (int)(i & 1023);
    int p = row >> 6;
    float v = 0.f;
    if (p < 5) {
        const float* src = (p == 0) ? a0 : (p == 1) ? a1 : (p == 2) ? a2
                         : (p == 3) ? a3 : a4;
        v = src[(long)(row & 63) * 1024 + col];
    }
    dst[i] = __float2half_rn(v);
}

__global__ void __launch_bounds__(256) pack_lb_kernel(
        const float* __restrict__ b0, const float* __restrict__ b1,
        const float* __restrict__ b2, const float* __restrict__ b3,
        const float* __restrict__ b4, __half* __restrict__ dstb,
        const float* __restrict__ l0, const float* __restrict__ l1,
        const float* __restrict__ l2, const float* __restrict__ l3,
        const float* __restrict__ l4, float* __restrict__ dstl) {
    long i = (long)blockIdx.x * 256 + threadIdx.x;   // 5*1024*64 + 5*1024
    if (i < 5ll * 1024 * 64) {
        int p = (int)(i >> 16);
        long r = i & 65535;
        const float* src = (p == 0) ? b0 : (p == 1) ? b1 : (p == 2) ? b2
                         : (p == 3) ? b3 : b4;
        dstb[i] = __float2half_rn(src[r]);
    } else {
        int j = (int)(i - 5ll * 1024 * 64);
        int p = j >> 10;
        int r = j & 1023;
        const float* src = (p == 0) ? l0 : (p == 1) ? l1 : (p == 2) ? l2
                         : (p == 3) ? l3 : l4;
        dstl[j] = src[r];
    }
}

__global__ void __launch_bounds__(256) pack_w_kernel(
        const float* __restrict__ w0, const float* __restrict__ w1,
        const float* __restrict__ w2, const float* __restrict__ w3,
        const float* __restrict__ w4, __half* __restrict__ dst) {
    long i = (long)blockIdx.x * 256 + threadIdx.x;
    int p = (int)(i >> 20);
    long r = i & 1048575;
    const float* src = (p == 0) ? w0 : (p == 1) ? w1 : (p == 2) ? w2
                     : (p == 3) ? w3 : w4;
    dst[i] = __float2half_rn(src[r]);
}

// t1 = half(tanh(p0 + p1))   (combine split-K partials)
__global__ void __launch_bounds__(256) combine_t1_kernel(
        const float* __restrict__ p, __half* __restrict__ dst) {
    long i = ((long)blockIdx.x * 256 + threadIdx.x) * 4;   // < 4096*384
    float4 a = *(const float4*)&p[i];
    float4 b = *(const float4*)&p[(long)BT * 384 + i];
    uint2 o = h4pack(tanhf(a.x + b.x), tanhf(a.y + b.y),
                     tanhf(a.z + b.z), tanhf(a.w + b.w));
    *(uint2*)&dst[i] = o;
}

// ---------------- fp16 tensor-core GEMM with fused epilogues ---------------
// tile C[128,128] = A[M,K] @ W[N,K]^T  (fp16 operands, fp32 accumulate)
// PROVEN R7 config: BKK=64, SLDH=72, 2-stage ping-pong, 2 CTAs/SM.
// MODE 0: Cf = acc                    (float out)
// MODE 1: Ch = half(tanh(acc))        (half out)
// MODE 2: Ch = half(x + dx*(acc+L))   (half out; x/dx row length 1024)
// MODE 3: Cf = exp(-exp(acc+L))       (float out)
#define BKK 64
#define SLDH 72
#define PIPEH (2*128*SLDH)
#define GSMEM (2*PIPEH*2)

template<int MODE>
__global__ void __launch_bounds__(256) gemm_h(
        const __half* __restrict__ A, long sAz, int lda,
        const __half* __restrict__ W, long sWz, int ldw,
        void* __restrict__ Cv, long sCz, int ldc,
        const float* __restrict__ L, long sLz,
        const float* __restrict__ x, const float* __restrict__ dx,
        int K) {
    using namespace nvcuda;
    extern __shared__ __half sm[];
    const int tid = threadIdx.x;
    const int z = blockIdx.z;
    A += (long)z * sAz;
    W += (long)z * sWz;
    if (MODE >= 2) L += (long)z * sLz;
    float* Cf = (float*)Cv + (long)z * sCz;
    __half* Ch = (__half*)Cv + (long)z * sCz;
    const int bm = blockIdx.y * 128;
    const int bn = blockIdx.x * 128;
    const int r = tid >> 3;
    const int q = (tid & 7) * 8;
    const __half* aP = A + (long)(bm + r) * lda + q;
    const __half* wP = W + (long)(bn + r) * ldw + q;
    unsigned dA = (unsigned)__cvta_generic_to_shared(sm) + (r * SLDH + q) * 2;
    const int wid = tid >> 5;
    const int wy = wid >> 1;
    const int wx = wid & 1;

    wmma::fragment<wmma::accumulator, 16, 16, 16, float> acc[2][4];
    #pragma unroll
    for (int i = 0; i < 2; i++)
        #pragma unroll
        for (int j = 0; j < 4; j++)
            wmma::fill_fragment(acc[i][j], 0.0f);

#define ISSUE(st, k0) do {                                                   \
        unsigned _a = dA + (st) * (PIPEH * 2);                               \
        unsigned _b = _a + 128 * SLDH * 2;                                   \
        _Pragma("unroll")                                                    \
        for (int _i = 0; _i < 4; _i++) {                                     \
            asm volatile("cp.async.cg.shared.global [%0], [%1], 16;\n" ::    \
                "r"(_a + _i * 32 * SLDH * 2),                                \
                "l"(aP + (long)_i * 32 * lda + (k0)));                       \
            asm volatile("cp.async.cg.shared.global [%0], [%1], 16;\n" ::    \
                "r"(_b + _i * 32 * SLDH * 2),                                \
                "l"(wP + (long)_i * 32 * ldw + (k0)));                       \
        }                                                                    \
        asm volatile("cp.async.commit_group;\n");                            \
    } while (0)

    const int nIter = K / BKK;
    ISSUE(0, 0);
    if (nIter > 1) {
        ISSUE(1, BKK);
        asm volatile("cp.async.wait_group 1;\n");
    } else {
        asm volatile("cp.async.wait_group 0;\n");
    }
    __syncthreads();

    for (int it = 0; it < nIter; it++) {
        int s = it & 1;
        const __half* sA = sm + s * PIPEH;
        const __half* sB = sA + 128 * SLDH;
        #pragma unroll
        for (int kk = 0; kk < BKK; kk += 16) {
            wmma::fragment<wmma::matrix_a, 16, 16, 16, __half, wmma::row_major> af[2];
            wmma::fragment<wmma::matrix_b, 16, 16, 16, __half, wmma::col_major> bf[4];
            #pragma unroll
            for (int i = 0; i < 2; i++)
                wmma::load_matrix_sync(af[i], sA + (wy * 32 + i * 16) * SLDH + kk, SLDH);
            #pragma unroll
            for (int j = 0; j < 4; j++)
                wmma::load_matrix_sync(bf[j], sB + (wx * 64 + j * 16) * SLDH + kk, SLDH);
            #pragma unroll
            for (int i = 0; i < 2; i++)
                #pragma unroll
                for (int j = 0; j < 4; j++)
                    wmma::mma_sync(acc[i][j], af[i], bf[j], acc[i][j]);
        }
        __syncthreads();
        if (it + 2 < nIter) {
            ISSUE(s, (it + 2) * BKK);
            asm volatile("cp.async.wait_group 1;\n");
            __syncthreads();
        } else if (it + 1 < nIter) {
            asm volatile("cp.async.wait_group 0;\n");
            __syncthreads();
        }
    }
#undef ISSUE

    if (MODE == 0) {
        #pragma unroll
        for (int i = 0; i < 2; i++)
            #pragma unroll
            for (int j = 0; j < 4; j++)
                wmma::store_matrix_sync(
                    Cf + (long)(bm + wy * 32 + i * 16) * ldc + bn + wx * 64 + j * 16,
                    acc[i][j], ldc, wmma::mem_row_major);
    } else {
        float* smf = reinterpret_cast<float*>(sm);
        __syncthreads();
        #pragma unroll
        for (int i = 0; i < 2; i++)
            #pragma unroll
            for (int j = 0; j < 4; j++)
                wmma::store_matrix_sync(
                    smf + (wy * 32 + i * 16) * 128 + wx * 64 + j * 16,
                    acc[i][j], 128, wmma::mem_row_major);
        __syncthreads();
        int row = tid >> 1;
        int c0 = (tid & 1) * 64;
        long gro = bm + row;
        #pragma unroll
        for (int i = 0; i < 16; i++) {
            int c = c0 + i * 4;
            float4 m = *(float4*)&smf[row * 128 + c];
            if (MODE == 1) {
                uint2 o = h4pack(tanhf(m.x), tanhf(m.y), tanhf(m.z), tanhf(m.w));
                *(uint2*)&Ch[gro * ldc + bn + c] = o;
            } else if (MODE == 2) {
                float4 lv = *(const float4*)&L[bn + c];
                long gi = gro * 1024 + bn + c;
                float4 xv = *(const float4*)&x[gi];
                float4 dv = *(const float4*)&dx[gi];
                uint2 o = h4pack(fmaf(dv.x, m.x + lv.x, xv.x),
                                 fmaf(dv.y, m.y + lv.y, xv.y),
                                 fmaf(dv.z, m.z + lv.z, xv.z),
                                 fmaf(dv.w, m.w + lv.w, xv.w));
                *(uint2*)&Ch[gro * ldc + bn + c] = o;
            } else {
                float4 lv = *(const float4*)&L[bn + c];
                float4 o;
                o.x = expf(-expf(m.x + lv.x));
                o.y = expf(-expf(m.y + lv.y));
                o.z = expf(-expf(m.z + lv.z));
                o.w = expf(-expf(m.w + lv.w));
                *(float4*)&Cf[gro * ldc + bn + c] = o;
            }
        }
    }
}

// ---------------- recurrent scan: 128 CTAs (column split) ------------------
__global__ void __launch_bounds__(256) scan2_kernel(
        const float* __restrict__ r, const float* __restrict__ w,
        const float* __restrict__ k, const float* __restrict__ v,
        const float* __restrict__ init_state, const float* __restrict__ u,
        float* __restrict__ y, float* __restrict__ state_out) {
    int cta = blockIdx.x;
    int bh = cta >> 1, jh = cta & 1;
    int b = bh / Hh, h = bh % Hh;
    int tid = threadIdx.x;
    int j32 = tid & 31;
    int gi = tid >> 5;
    int j = jh * 32 + j32;
    __shared__ float shr[64], shw[64], shk[64], shv[32];
    __shared__ float ypart[2][8][32];
    float S[8], uu[8];
    #pragma unroll
    for (int ii = 0; ii < 8; ii++) {
        int i = gi * 8 + ii;
        S[ii] = init_state[(long)(h * 64 + i) * 64 + j];
        uu[ii] = u[h * 64 + i];
    }
    long base = (long)b * Tt * Dd + (long)h * 64;
    const float* myp = nullptr;
    float* slot = nullptr;
    if (tid < 64)       { myp = r + base + tid;               slot = &shr[tid]; }
    else if (tid < 128) { myp = w + base + (tid - 64);        slot = &shw[tid - 64]; }
    else if (tid < 192) { myp = k + base + (tid - 128);       slot = &shk[tid - 128]; }
    else if (tid < 224) { myp = v + base + jh * 32 + (tid - 192); slot = &shv[tid - 192]; }
    float pref = myp ? myp[0] : 0.f;
    for (int t = 0; t < Tt; t++) {
        if (slot) *slot = pref;
        __syncthreads();
        if (myp && t + 1 < Tt) pref = myp[(long)(t + 1) * Dd];
        float vj = shv[j32];
        float acc = 0.f;
        #pragma unroll
        for (int ii = 0; ii < 8; ii++) {
            int i = gi * 8 + ii;
            float kv = shk[i] * vj;
            acc = fmaf(shr[i], fmaf(uu[ii], kv, S[ii]), acc);
            S[ii] = fmaf(shw[i], S[ii], kv);
        }
        ypart[t & 1][gi][j32] = acc;
        __syncthreads();
        if (gi == 0) {
            float yy = 0.f;
            #pragma unroll
            for (int g2 = 0; g2 < 8; g2++) yy += ypart[t & 1][g2][j32];
            y[base + (long)t * Dd + j] = yy;
        }
    }
    #pragma unroll
    for (int ii = 0; ii < 8; ii++) {
        int i = gi * 8 + ii;
        state_out[(long)((b * Hh + h) * 64 + i) * 64 + j] = S[ii];
    }
}

// ---------------- groupnorm + silu gate ------------------------------------
__global__ void __launch_bounds__(256) gn_gate_kernel(
        const float* __restrict__ y, const float* __restrict__ g,
        const float* __restrict__ lnw, const float* __restrict__ lnb,
        __half* __restrict__ out) {
    long warp = ((long)blockIdx.x * blockDim.x + threadIdx.x) >> 5;
    int lane = threadIdx.x & 31;
    if (warp >= (long)Bb * Tt * Hh) return;
    const float* yp = y + warp * 64;
    float v0 = yp[lane], v1 = yp[lane + 32];
    float s = v0 + v1;
    #pragma unroll
    for (int off = 16; off > 0; off >>= 1) s += __shfl_xor_sync(0xffffffffu, s, off);
    float mean = s * (1.f / 64.f);
    float d0 = v0 - mean, d1 = v1 - mean;
    float vs = d0 * d0 + d1 * d1;
    #pragma unroll
    for (int off = 16; off > 0; off >>= 1) vs += __shfl_xor_sync(0xffffffffu, vs, off);
    float inv = rsqrtf(vs * (1.f / 64.f) + 1e-5f);
    float n0 = fmaf(d0 * inv, lnw[lane], lnb[lane]);
    float n1 = fmaf(d1 * inv, lnw[lane + 32], lnb[lane + 32]);
    float g0 = g[warp * 64 + lane];
    float g1 = g[warp * 64 + lane + 32];
    float s0 = g0 / (1.f + expf(-g0));
    float s1 = g1 / (1.f + expf(-g1));
    out[warp * 64 + lane] = __float2half_rn(s0 * n0);
    out[warp * 64 + lane + 32] = __float2half_rn(s1 * n1);
}

// ---------------- host -----------------------------------------------------
static void* symaddr(const void* s) {
    void* p = nullptr;
    cudaGetSymbolAddress(&p, s);
    return p;
}

extern "C" void kernel_launch(void* const* d_in, const int* in_sizes, int n_in,
                              void* d_out, int out_size) {
    (void)in_sizes; (void)n_in;
    const float* x    = (const float*)d_in[0];
    const float* xw   = (const float*)d_in[1];
    const float* rW   = (const float*)d_in[2];
    const float* kW   = (const float*)d_in[3];
    const float* vW   = (const float*)d_in[4];
    const float* gW   = (const float*)d_in[5];
    const float* la[5] = {(const float*)d_in[6],  (const float*)d_in[9],
                          (const float*)d_in[12], (const float*)d_in[15],
                          (const float*)d_in[18]};
    const float* lb[5] = {(const float*)d_in[7],  (const float*)d_in[10],
                          (const float*)d_in[13], (const float*)d_in[16],
                          (const float*)d_in[19]};
    const float* ll[5] = {(const float*)d_in[8],  (const float*)d_in[11],
                          (const float*)d_in[14], (const float*)d_in[17],
                          (const float*)d_in[20]};
    const float* ln_w = (const float*)d_in[21];
    const float* ln_b = (const float*)d_in[22];
    const float* oW   = (const float*)d_in[23];
    const float* init_state = (const float*)d_in[24];
    const float* u    = (const float*)d_in[25];

    float* out = (float*)d_out;

    float*  p_dx    = (float*)symaddr(g_dx);
    __half* p_lerpx = (__half*)symaddr(g_lerpx);
    __half* p_in    = (__half*)symaddr(g_in);
    __half* p_t1    = (__half*)symaddr(g_t1);
    float*  p_s1p   = (float*)symaddr(g_s1p);
    __half* p_t2    = (__half*)symaddr(g_t2);
    __half* p_laP   = (__half*)symaddr(g_laP);
    __half* p_lbP   = (__half*)symaddr(g_lbP);
    float*  p_llP   = (float*)symaddr(g_llP);
    __half* p_W5    = (__half*)symaddr(g_W5);
    float*  p_w     = (float*)symaddr(g_w);
    float*  p_proj  = (float*)symaddr(g_proj);
    float*  p_y     = (float*)symaddr(g_y);
    __half* p_opre  = (__half*)symaddr(g_opre);
    float*  p_stfb  = (float*)symaddr(g_stfb);

    static cudaStream_t sA = nullptr, sB = nullptr;
    static cudaEvent_t eF = nullptr, eW = nullptr, eL = nullptr,
                       eWG = nullptr, eP = nullptr, eG = nullptr, eB = nullptr;
    if (!sA) {
        cudaStreamCreateWithFlags(&sA, cudaStreamNonBlocking);
        cudaStreamCreateWithFlags(&sB, cudaStreamNonBlocking);
        cudaEventCreateWithFlags(&eF, cudaEventDisableTiming);
        cudaEventCreateWithFlags(&eW, cudaEventDisableTiming);
        cudaEventCreateWithFlags(&eL, cudaEventDisableTiming);
        cudaEventCreateWithFlags(&eWG, cudaEventDisableTiming);
        cudaEventCreateWithFlags(&eP, cudaEventDisableTiming);
        cudaEventCreateWithFlags(&eG, cudaEventDisableTiming);
        cudaEventCreateWithFlags(&eB, cudaEventDisableTiming);
        cudaFuncSetAttribute(gemm_h<0>, cudaFuncAttributeMaxDynamicSharedMemorySize, GSMEM);
        cudaFuncSetAttribute(gemm_h<1>, cudaFuncAttributeMaxDynamicSharedMemorySize, GSMEM);
        cudaFuncSetAttribute(gemm_h<2>, cudaFuncAttributeMaxDynamicSharedMemorySize, GSMEM);
        cudaFuncSetAttribute(gemm_h<3>, cudaFuncAttributeMaxDynamicSharedMemorySize, GSMEM);
    }

    // ---- forks: packs run off the critical path
    cudaEventRecord(eF, 0);
    cudaStreamWaitEvent(sA, eF, 0);
    pack_w_kernel<<<(5 * 1024 * 1024) / 256, 256, 0, sA>>>(rW, kW, vW, gW, oW, p_W5);
    cudaEventRecord(eW, sA);
    cudaStreamWaitEvent(sB, eF, 0);
    pack_la_kernel<<<(384 * 1024) / 256, 256, 0, sB>>>(la[0], la[1], la[2], la[3], la[4], p_laP);
    pack_lb_kernel<<<(5 * 1024 * 64 + 5 * 1024 + 255) / 256, 256, 0, sB>>>(
        lb[0], lb[1], lb[2], lb[3], lb[4], p_lbP,
        ll[0], ll[1], ll[2], ll[3], ll[4], p_llP);
    cudaEventRecord(eB, sB);

    // ---- main chain
    premix_kernel<<<(int)(BTD / 1024), 256>>>(x, xw, p_dx, p_lerpx);

    // lora stage 1, split-K z=2: s1p[z] = lerpx[:, z*512:] @ laP[:, z*512:]^T
    cudaStreamWaitEvent(0, eB, 0);
    gemm_h<0><<<dim3(3, 32, 2), 256, GSMEM>>>(
        p_lerpx, 512, 1024, p_laP, 512, 1024, p_s1p, (long)BT * 384, 384,
        nullptr, 0, nullptr, nullptr, 512);
    combine_t1_kernel<<<(BT * 384) / 1024, 256>>>(p_s1p, p_t1);

    // fused lora stage 2 + mix, all 5 paths
    gemm_h<2><<<dim3(8, 32, 5), 256, GSMEM>>>(
        p_t1, 64, 384, p_lbP, 65536, 64, p_in, BTD, 1024,
        p_llP, 1024, x, p_dx, 64);

    // ---- fork: d-lora second pass (t2, w) on sA, parallel with projections
    cudaEventRecord(eL, 0);
    cudaStreamWaitEvent(sA, eL, 0);
    gemm_h<1><<<dim3(1, 32, 1), 256, GSMEM, sA>>>(
        p_in + 4 * BTD, 0, 1024, p_laP + 256 * 1024, 0, 1024, p_t2, 0, 128,
        nullptr, 0, nullptr, nullptr, 1024);
    gemm_h<3><<<dim3(8, 32, 1), 256, GSMEM, sA>>>(
        p_t2, 0, 128, p_lbP + 4 * 65536, 0, 64, p_w, 0, 1024,
        p_llP + 4 * 1024, 0, nullptr, nullptr, 64);
    cudaEventRecord(eWG, sA);

    // ---- r,k,v projections (need packed weights)
    cudaStreamWaitEvent(0, eW, 0);
    gemm_h<0><<<dim3(8, 32, 3), 256, GSMEM>>>(
        p_in, BTD, 1024, p_W5, 1024 * 1024, 1024, p_proj, BTD, 1024,
        nullptr, 0, nullptr, nullptr, 1024);

    // ---- fork: g projection on sB, parallel with the scan
    cudaEventRecord(eP, 0);
    cudaStreamWaitEvent(sB, eP, 0);
    gemm_h<0><<<dim3(8, 32, 1), 256, GSMEM, sB>>>(
        p_in + 3 * BTD, 0, 1024, p_W5 + 3ll * 1024 * 1024, 0, 1024,
        p_proj + 3 * BTD, 0, 1024, nullptr, 0, nullptr, nullptr, 1024);
    cudaEventRecord(eG, sB);

    // ---- recurrent scan (needs r,k,v + w)
    cudaStreamWaitEvent(0, eWG, 0);
    float* st_out = (out_size >= (int)(BTD + STATE)) ? (out + BTD) : p_stfb;
    scan2_kernel<<<2 * Bb * Hh, 256>>>(p_proj, p_w, p_proj + BTD, p_proj + 2 * BTD,
                                       init_state, u, p_y, st_out);

    // ---- gate (needs g) + output projection
    cudaStreamWaitEvent(0, eG, 0);
    gn_gate_kernel<<<(Bb * Tt * Hh) / 8, 256>>>(p_y, p_proj + 3 * BTD, ln_w, ln_b, p_opre);
    gemm_h<0><<<dim3(8, 32, 1), 256, GSMEM>>>(
        p_opre, 0, 1024, p_W5 + 4ll * 1024 * 1024, 0, 1024, out, 0, 1024,
        nullptr, 0, nullptr, nullptr, 1024);
}

// round 11
// speedup vs baseline: 1.2636x; 1.1848x over previous
#include <cuda_runtime.h>
#include <cuda_fp16.h>
#include <mma.h>
#include <math.h>

#define Bb 4
#define Tt 1024
#define Dd 1024
#define Hh 16
#define HDh 64
#define LR 64
#define BT (Bb*Tt)             /* 4096 */
#define BTD ((long)BT*Dd)      /* 4194304 */
#define STATE (Bb*Hh*HDh*HDh)  /* 262144 */

// ---------------- scratch (device globals; no allocation allowed) ----------
__device__ float  g_dx[BTD];
__device__ __half g_lerpx[BTD];
__device__ __half g_in[5*BTD];
__device__ __half g_t1[(long)BT*384];
__device__ float  g_s1p[2ll*BT*384];   // split-K partials for stage1
__device__ __half g_t2[(long)BT*128];
__device__ __half g_laP[384*1024];
__device__ __half g_lbP[5*1024*64];
__device__ float  g_llP[5*1024];
__device__ __half g_W5[5ll*1024*1024];
__device__ float  g_w[BTD];
__device__ float  g_proj[4*BTD];
__device__ float  g_y[BTD];
__device__ __half g_opre[BTD];
__device__ float  g_stfb[STATE];

__device__ __forceinline__ uint2 h4pack(float a, float b, float c, float d) {
    __half2 p0 = __floats2half2_rn(a, b);
    __half2 p1 = __floats2half2_rn(c, d);
    uint2 r;
    r.x = *reinterpret_cast<unsigned*>(&p0);
    r.y = *reinterpret_cast<unsigned*>(&p1);
    return r;
}

// ---------------- elementwise / pack kernels -------------------------------

// vectorized: 4 elements per thread
__global__ void __launch_bounds__(256) premix_kernel(
        const float* __restrict__ x, const float* __restrict__ xw,
        float* __restrict__ dx, __half* __restrict__ lerpx) {
    long idx = ((long)blockIdx.x * 256 + threadIdx.x) * 4;
    int dd = (int)(idx % Dd);
    long bt = idx / Dd;
    int t = (int)(bt % Tt);
    float4 xv = *(const float4*)&x[idx];
    float4 xp = make_float4(0.f, 0.f, 0.f, 0.f);
    if (t > 0) xp = *(const float4*)&x[idx - Dd];
    float4 wv = *(const float4*)&xw[dd];
    float4 d;
    d.x = xp.x - xv.x; d.y = xp.y - xv.y;
    d.z = xp.z - xv.z; d.w = xp.w - xv.w;
    *(float4*)&dx[idx] = d;
    uint2 o = h4pack(fmaf(d.x, wv.x, xv.x), fmaf(d.y, wv.y, xv.y),
                     fmaf(d.z, wv.z, xv.z), fmaf(d.w, wv.w, xv.w));
    *(uint2*)&lerpx[idx] = o;
}

__global__ void __launch_bounds__(256) pack_la_kernel(
        const float* __restrict__ a0, const float* __restrict__ a1,
        const float* __restrict__ a2, const float* __restrict__ a3,
        const float* __restrict__ a4, __half* __restrict__ dst) {
    long i = (long)blockIdx.x * 256 + threadIdx.x;
    int row = (int)(i >> 10);
    int col = (int)(i & 1023);
    int p = row >> 6;
    float v = 0.f;
    if (p < 5) {
        const float* src = (p == 0) ? a0 : (p == 1) ? a1 : (p == 2) ? a2
                         : (p == 3) ? a3 : a4;
        v = src[(long)(row & 63) * 1024 + col];
    }
    dst[i] = __float2half_rn(v);
}

__global__ void __launch_bounds__(256) pack_lb_kernel(
        const float* __restrict__ b0, const float* __restrict__ b1,
        const float* __restrict__ b2, const float* __restrict__ b3,
        const float* __restrict__ b4, __half* __restrict__ dstb,
        const float* __restrict__ l0, const float* __restrict__ l1,
        const float* __restrict__ l2, const float* __restrict__ l3,
        const float* __restrict__ l4, float* __restrict__ dstl) {
    long i = (long)blockIdx.x * 256 + threadIdx.x;   // 5*1024*64 + 5*1024
    if (i < 5ll * 1024 * 64) {
        int p = (int)(i >> 16);
        long r = i & 65535;
        const float* src = (p == 0) ? b0 : (p == 1) ? b1 : (p == 2) ? b2
                         : (p == 3) ? b3 : b4;
        dstb[i] = __float2half_rn(src[r]);
    } else {
        int j = (int)(i - 5ll * 1024 * 64);
        int p = j >> 10;
        int r = j & 1023;
        const float* src = (p == 0) ? l0 : (p == 1) ? l1 : (p == 2) ? l2
                         : (p == 3) ? l3 : l4;
        dstl[j] = src[r];
    }
}

__global__ void __launch_bounds__(256) pack_w_kernel(
        const float* __restrict__ w0, const float* __restrict__ w1,
        const float* __restrict__ w2, const float* __restrict__ w3,
        const float* __restrict__ w4, __half* __restrict__ dst) {
    long i = (long)blockIdx.x * 256 + threadIdx.x;
    int p = (int)(i >> 20);
    long r = i & 1048575;
    const float* src = (p == 0) ? w0 : (p == 1) ? w1 : (p == 2) ? w2
                     : (p == 3) ? w3 : w4;
    dst[i] = __float2half_rn(src[r]);
}

// t1 = half(tanh(p0 + p1))   (combine split-K partials)
__global__ void __launch_bounds__(256) combine_t1_kernel(
        const float* __restrict__ p, __half* __restrict__ dst) {
    long i = ((long)blockIdx.x * 256 + threadIdx.x) * 4;   // < 4096*384
    float4 a = *(const float4*)&p[i];
    float4 b = *(const float4*)&p[(long)BT * 384 + i];
    uint2 o = h4pack(tanhf(a.x + b.x), tanhf(a.y + b.y),
                     tanhf(a.z + b.z), tanhf(a.w + b.w));
    *(uint2*)&dst[i] = o;
}

// ---------------- fp16 tensor-core GEMM with fused epilogues ---------------
// tile C[128,128] = A[M,K] @ W[N,K]^T  (fp16 operands, fp32 accumulate)
// PROVEN config: BKK=64, SLDH=72, 2-stage ping-pong, 2 CTAs/SM.
// MODE 0: Cf = acc                    (float out)
// MODE 1: Ch = half(tanh(acc))        (half out)
// MODE 2: Ch = half(x + dx*(acc+L))   (half out; x/dx row length 1024)
// MODE 3: Cf = exp(-exp(acc+L))       (float out)
#define BKK 64
#define SLDH 72
#define PIPEH (2*128*SLDH)
#define GSMEM (2*PIPEH*2)

template<int MODE>
__global__ void __launch_bounds__(256) gemm_h(
        const __half* __restrict__ A, long sAz, int lda,
        const __half* __restrict__ W, long sWz, int ldw,
        void* __restrict__ Cv, long sCz, int ldc,
        const float* __restrict__ L, long sLz,
        const float* __restrict__ x, const float* __restrict__ dx,
        int K) {
    using namespace nvcuda;
    extern __shared__ __half sm[];
    const int tid = threadIdx.x;
    const int z = blockIdx.z;
    A += (long)z * sAz;
    W += (long)z * sWz;
    if (MODE >= 2) L += (long)z * sLz;
    float* Cf = (float*)Cv + (long)z * sCz;
    __half* Ch = (__half*)Cv + (long)z * sCz;
    const int bm = blockIdx.y * 128;
    const int bn = blockIdx.x * 128;
    const int r = tid >> 3;
    const int q = (tid & 7) * 8;
    const __half* aP = A + (long)(bm + r) * lda + q;
    const __half* wP = W + (long)(bn + r) * ldw + q;
    unsigned dA = (unsigned)__cvta_generic_to_shared(sm) + (r * SLDH + q) * 2;
    const int wid = tid >> 5;
    const int wy = wid >> 1;
    const int wx = wid & 1;

    wmma::fragment<wmma::accumulator, 16, 16, 16, float> acc[2][4];
    #pragma unroll
    for (int i = 0; i < 2; i++)
        #pragma unroll
        for (int j = 0; j < 4; j++)
            wmma::fill_fragment(acc[i][j], 0.0f);

#define ISSUE(st, k0) do {                                                   \
        unsigned _a = dA + (st) * (PIPEH * 2);                               \
        unsigned _b = _a + 128 * SLDH * 2;                                   \
        _Pragma("unroll")                                                    \
        for (int _i = 0; _i < 4; _i++) {                                     \
            asm volatile("cp.async.cg.shared.global [%0], [%1], 16;\n" ::    \
                "r"(_a + _i * 32 * SLDH * 2),                                \
                "l"(aP + (long)_i * 32 * lda + (k0)));                       \
            asm volatile("cp.async.cg.shared.global [%0], [%1], 16;\n" ::    \
                "r"(_b + _i * 32 * SLDH * 2),                                \
                "l"(wP + (long)_i * 32 * ldw + (k0)));                       \
        }                                                                    \
        asm volatile("cp.async.commit_group;\n");                            \
    } while (0)

    const int nIter = K / BKK;
    ISSUE(0, 0);
    if (nIter > 1) {
        ISSUE(1, BKK);
        asm volatile("cp.async.wait_group 1;\n");
    } else {
        asm volatile("cp.async.wait_group 0;\n");
    }
    __syncthreads();

    for (int it = 0; it < nIter; it++) {
        int s = it & 1;
        const __half* sA = sm + s * PIPEH;
        const __half* sB = sA + 128 * SLDH;
        #pragma unroll
        for (int kk = 0; kk < BKK; kk += 16) {
            wmma::fragment<wmma::matrix_a, 16, 16, 16, __half, wmma::row_major> af[2];
            wmma::fragment<wmma::matrix_b, 16, 16, 16, __half, wmma::col_major> bf[4];
            #pragma unroll
            for (int i = 0; i < 2; i++)
                wmma::load_matrix_sync(af[i], sA + (wy * 32 + i * 16) * SLDH + kk, SLDH);
            #pragma unroll
            for (int j = 0; j < 4; j++)
                wmma::load_matrix_sync(bf[j], sB + (wx * 64 + j * 16) * SLDH + kk, SLDH);
            #pragma unroll
            for (int i = 0; i < 2; i++)
                #pragma unroll
                for (int j = 0; j < 4; j++)
                    wmma::mma_sync(acc[i][j], af[i], bf[j], acc[i][j]);
        }
        __syncthreads();
        if (it + 2 < nIter) {
            ISSUE(s, (it + 2) * BKK);
            asm volatile("cp.async.wait_group 1;\n");
            __syncthreads();
        } else if (it + 1 < nIter) {
            asm volatile("cp.async.wait_group 0;\n");
            __syncthreads();
        }
    }
#undef ISSUE

    if (MODE == 0) {
        #pragma unroll
        for (int i = 0; i < 2; i++)
            #pragma unroll
            for (int j = 0; j < 4; j++)
                wmma::store_matrix_sync(
                    Cf + (long)(bm + wy * 32 + i * 16) * ldc + bn + wx * 64 + j * 16,
                    acc[i][j], ldc, wmma::mem_row_major);
    } else {
        float* smf = reinterpret_cast<float*>(sm);
        __syncthreads();
        #pragma unroll
        for (int i = 0; i < 2; i++)
            #pragma unroll
            for (int j = 0; j < 4; j++)
                wmma::store_matrix_sync(
                    smf + (wy * 32 + i * 16) * 128 + wx * 64 + j * 16,
                    acc[i][j], 128, wmma::mem_row_major);
        __syncthreads();
        int row = tid >> 1;
        int c0 = (tid & 1) * 64;
        long gro = bm + row;
        #pragma unroll
        for (int i = 0; i < 16; i++) {
            int c = c0 + i * 4;
            float4 m = *(float4*)&smf[row * 128 + c];
            if (MODE == 1) {
                uint2 o = h4pack(tanhf(m.x), tanhf(m.y), tanhf(m.z), tanhf(m.w));
                *(uint2*)&Ch[gro * ldc + bn + c] = o;
            } else if (MODE == 2) {
                float4 lv = *(const float4*)&L[bn + c];
                long gi = gro * 1024 + bn + c;
                float4 xv = *(const float4*)&x[gi];
                float4 dv = *(const float4*)&dx[gi];
                uint2 o = h4pack(fmaf(dv.x, m.x + lv.x, xv.x),
                                 fmaf(dv.y, m.y + lv.y, xv.y),
                                 fmaf(dv.z, m.z + lv.z, xv.z),
                                 fmaf(dv.w, m.w + lv.w, xv.w));
                *(uint2*)&Ch[gro * ldc + bn + c] = o;
            } else {
                float4 lv = *(const float4*)&L[bn + c];
                float4 o;
                o.x = expf(-expf(m.x + lv.x));
                o.y = expf(-expf(m.y + lv.y));
                o.z = expf(-expf(m.z + lv.z));
                o.w = expf(-expf(m.w + lv.w));
                *(float4*)&Cf[gro * ldc + bn + c] = o;
            }
        }
    }
}

// ---------------- recurrent scan: 128 CTAs, ONE sync per timestep ----------
// smem role layout (soff = tid for tid < 224): r:0..63  w:64..127  k:128..191  v:192..223
__global__ void __launch_bounds__(256) scan3_kernel(
        const float* __restrict__ r, const float* __restrict__ w,
        const float* __restrict__ k, const float* __restrict__ v,
        const float* __restrict__ init_state, const float* __restrict__ u,
        float* __restrict__ y, float* __restrict__ state_out) {
    int cta = blockIdx.x;
    int bh = cta >> 1, jh = cta & 1;
    int b = bh / Hh, h = bh % Hh;
    int tid = threadIdx.x;
    int j32 = tid & 31;
    int gi = tid >> 5;
    int j = jh * 32 + j32;
    __shared__ float sh[2][224];
    __shared__ float ypart[2][8][32];
    float S[8], uu[8];
    #pragma unroll
    for (int ii = 0; ii < 8; ii++) {
        int i = gi * 8 + ii;
        S[ii] = init_state[(long)(h * 64 + i) * 64 + j];
        uu[ii] = u[h * 64 + i];
    }
    long base = (long)b * Tt * Dd + (long)h * 64;
    const float* myp = nullptr;
    if (tid < 64)       myp = r + base + tid;
    else if (tid < 128) myp = w + base + (tid - 64);
    else if (tid < 192) myp = k + base + (tid - 128);
    else if (tid < 224) myp = v + base + jh * 32 + (tid - 192);

    // prologue: stage t=0, prefetch t=1
    if (tid < 224) sh[0][tid] = myp[0];
    __syncthreads();
    float pref = (tid < 224) ? myp[Dd] : 0.f;   // Tt > 1 always

    for (int t = 0; t < Tt; t++) {
        int cur = t & 1, nxt = cur ^ 1;
        float vj = sh[cur][192 + j32];
        float acc = 0.f;
        #pragma unroll
        for (int ii = 0; ii < 8; ii++) {
            int i = gi * 8 + ii;
            float kv = sh[cur][128 + i] * vj;
            acc = fmaf(sh[cur][i], fmaf(uu[ii], kv, S[ii]), acc);
            S[ii] = fmaf(sh[cur][64 + i], S[ii], kv);
        }
        ypart[cur][gi][j32] = acc;
        if (tid < 224) {
            sh[nxt][tid] = pref;
            if (t + 2 < Tt) pref = myp[(long)(t + 2) * Dd];
        }
        __syncthreads();
        if (gi == 0) {
            float yy = 0.f;
            #pragma unroll
            for (int g2 = 0; g2 < 8; g2++) yy += ypart[cur][g2][j32];
            y[base + (long)t * Dd + j] = yy;
        }
    }
    #pragma unroll
    for (int ii = 0; ii < 8; ii++) {
        int i = gi * 8 + ii;
        state_out[(long)((b * Hh + h) * 64 + i) * 64 + j] = S[ii];
    }
}

// ---------------- groupnorm + silu gate ------------------------------------
__global__ void __launch_bounds__(256) gn_gate_kernel(
        const float* __restrict__ y, const float* __restrict__ g,
        const float* __restrict__ lnw, const float* __restrict__ lnb,
        __half* __restrict__ out) {
    long warp = ((long)blockIdx.x * blockDim.x + threadIdx.x) >> 5;
    int lane = threadIdx.x & 31;
    if (warp >= (long)Bb * Tt * Hh) return;
    const float* yp = y + warp * 64;
    float v0 = yp[lane], v1 = yp[lane + 32];
    float s = v0 + v1;
    #pragma unroll
    for (int off = 16; off > 0; off >>= 1) s += __shfl_xor_sync(0xffffffffu, s, off);
    float mean = s * (1.f / 64.f);
    float d0 = v0 - mean, d1 = v1 - mean;
    float vs = d0 * d0 + d1 * d1;
    #pragma unroll
    for (int off = 16; off > 0; off >>= 1) vs += __shfl_xor_sync(0xffffffffu, vs, off);
    float inv = rsqrtf(vs * (1.f / 64.f) + 1e-5f);
    float n0 = fmaf(d0 * inv, lnw[lane], lnb[lane]);
    float n1 = fmaf(d1 * inv, lnw[lane + 32], lnb[lane + 32]);
    float g0 = g[warp * 64 + lane];
    float g1 = g[warp * 64 + lane + 32];
    float s0 = g0 / (1.f + expf(-g0));
    float s1 = g1 / (1.f + expf(-g1));
    out[warp * 64 + lane] = __float2half_rn(s0 * n0);
    out[warp * 64 + lane + 32] = __float2half_rn(s1 * n1);
}

// ---------------- host -----------------------------------------------------
static void* symaddr(const void* s) {
    void* p = nullptr;
    cudaGetSymbolAddress(&p, s);
    return p;
}

extern "C" void kernel_launch(void* const* d_in, const int* in_sizes, int n_in,
                              void* d_out, int out_size) {
    (void)in_sizes; (void)n_in;
    const float* x    = (const float*)d_in[0];
    const float* xw   = (const float*)d_in[1];
    const float* rW   = (const float*)d_in[2];
    const float* kW   = (const float*)d_in[3];
    const float* vW   = (const float*)d_in[4];
    const float* gW   = (const float*)d_in[5];
    const float* la[5] = {(const float*)d_in[6],  (const float*)d_in[9],
                          (const float*)d_in[12], (const float*)d_in[15],
                          (const float*)d_in[18]};
    const float* lb[5] = {(const float*)d_in[7],  (const float*)d_in[10],
                          (const float*)d_in[13], (const float*)d_in[16],
                          (const float*)d_in[19]};
    const float* ll[5] = {(const float*)d_in[8],  (const float*)d_in[11],
                          (const float*)d_in[14], (const float*)d_in[17],
                          (const float*)d_in[20]};
    const float* ln_w = (const float*)d_in[21];
    const float* ln_b = (const float*)d_in[22];
    const float* oW   = (const float*)d_in[23];
    const float* init_state = (const float*)d_in[24];
    const float* u    = (const float*)d_in[25];

    float* out = (float*)d_out;

    float*  p_dx    = (float*)symaddr(g_dx);
    __half* p_lerpx = (__half*)symaddr(g_lerpx);
    __half* p_in    = (__half*)symaddr(g_in);
    __half* p_t1    = (__half*)symaddr(g_t1);
    float*  p_s1p   = (float*)symaddr(g_s1p);
    __half* p_t2    = (__half*)symaddr(g_t2);
    __half* p_laP   = (__half*)symaddr(g_laP);
    __half* p_lbP   = (__half*)symaddr(g_lbP);
    float*  p_llP   = (float*)symaddr(g_llP);
    __half* p_W5    = (__half*)symaddr(g_W5);
    float*  p_w     = (float*)symaddr(g_w);
    float*  p_proj  = (float*)symaddr(g_proj);
    float*  p_y     = (float*)symaddr(g_y);
    __half* p_opre  = (__half*)symaddr(g_opre);
    float*  p_stfb  = (float*)symaddr(g_stfb);

    static cudaStream_t sA = nullptr, sB = nullptr;
    static cudaEvent_t eF = nullptr, eW = nullptr, eL = nullptr,
                       eWG = nullptr, eP = nullptr, eG = nullptr, eB = nullptr;
    if (!sA) {
        cudaStreamCreateWithFlags(&sA, cudaStreamNonBlocking);
        cudaStreamCreateWithFlags(&sB, cudaStreamNonBlocking);
        cudaEventCreateWithFlags(&eF, cudaEventDisableTiming);
        cudaEventCreateWithFlags(&eW, cudaEventDisableTiming);
        cudaEventCreateWithFlags(&eL, cudaEventDisableTiming);
        cudaEventCreateWithFlags(&eWG, cudaEventDisableTiming);
        cudaEventCreateWithFlags(&eP, cudaEventDisableTiming);
        cudaEventCreateWithFlags(&eG, cudaEventDisableTiming);
        cudaEventCreateWithFlags(&eB, cudaEventDisableTiming);
        cudaFuncSetAttribute(gemm_h<0>, cudaFuncAttributeMaxDynamicSharedMemorySize, GSMEM);
        cudaFuncSetAttribute(gemm_h<1>, cudaFuncAttributeMaxDynamicSharedMemorySize, GSMEM);
        cudaFuncSetAttribute(gemm_h<2>, cudaFuncAttributeMaxDynamicSharedMemorySize, GSMEM);
        cudaFuncSetAttribute(gemm_h<3>, cudaFuncAttributeMaxDynamicSharedMemorySize, GSMEM);
    }

    // ---- forks: packs run off the critical path
    cudaEventRecord(eF, 0);
    cudaStreamWaitEvent(sA, eF, 0);
    pack_w_kernel<<<(5 * 1024 * 1024) / 256, 256, 0, sA>>>(rW, kW, vW, gW, oW, p_W5);
    cudaEventRecord(eW, sA);
    cudaStreamWaitEvent(sB, eF, 0);
    pack_la_kernel<<<(384 * 1024) / 256, 256, 0, sB>>>(la[0], la[1], la[2], la[3], la[4], p_laP);
    pack_lb_kernel<<<(5 * 1024 * 64 + 5 * 1024 + 255) / 256, 256, 0, sB>>>(
        lb[0], lb[1], lb[2], lb[3], lb[4], p_lbP,
        ll[0], ll[1], ll[2], ll[3], ll[4], p_llP);
    cudaEventRecord(eB, sB);

    // ---- main chain
    premix_kernel<<<(int)(BTD / 1024), 256>>>(x, xw, p_dx, p_lerpx);

    // lora stage 1, split-K z=2: s1p[z] = lerpx[:, z*512:] @ laP[:, z*512:]^T
    cudaStreamWaitEvent(0, eB, 0);
    gemm_h<0><<<dim3(3, 32, 2), 256, GSMEM>>>(
        p_lerpx, 512, 1024, p_laP, 512, 1024, p_s1p, (long)BT * 384, 384,
        nullptr, 0, nullptr, nullptr, 512);
    combine_t1_kernel<<<(BT * 384) / 1024, 256>>>(p_s1p, p_t1);

    // fused lora stage 2 + mix, all 5 paths
    gemm_h<2><<<dim3(8, 32, 5), 256, GSMEM>>>(
        p_t1, 64, 384, p_lbP, 65536, 64, p_in, BTD, 1024,
        p_llP, 1024, x, p_dx, 64);

    // ---- fork: d-lora second pass (t2, w) on sA, parallel with projections
    cudaEventRecord(eL, 0);
    cudaStreamWaitEvent(sA, eL, 0);
    gemm_h<1><<<dim3(1, 32, 1), 256, GSMEM, sA>>>(
        p_in + 4 * BTD, 0, 1024, p_laP + 256 * 1024, 0, 1024, p_t2, 0, 128,
        nullptr, 0, nullptr, nullptr, 1024);
    gemm_h<3><<<dim3(8, 32, 1), 256, GSMEM, sA>>>(
        p_t2, 0, 128, p_lbP + 4 * 65536, 0, 64, p_w, 0, 1024,
        p_llP + 4 * 1024, 0, nullptr, nullptr, 64);
    cudaEventRecord(eWG, sA);

    // ---- r,k,v projections (need packed weights)
    cudaStreamWaitEvent(0, eW, 0);
    gemm_h<0><<<dim3(8, 32, 3), 256, GSMEM>>>(
        p_in, BTD, 1024, p_W5, 1024 * 1024, 1024, p_proj, BTD, 1024,
        nullptr, 0, nullptr, nullptr, 1024);

    // ---- fork: g projection on sB, parallel with the scan
    cudaEventRecord(eP, 0);
    cudaStreamWaitEvent(sB, eP, 0);
    gemm_h<0><<<dim3(8, 32, 1), 256, GSMEM, sB>>>(
        p_in + 3 * BTD, 0, 1024, p_W5 + 3ll * 1024 * 1024, 0, 1024,
        p_proj + 3 * BTD, 0, 1024, nullptr, 0, nullptr, nullptr, 1024);
    cudaEventRecord(eG, sB);

    // ---- recurrent scan (needs r,k,v + w)
    cudaStreamWaitEvent(0, eWG, 0);
    float* st_out = (out_size >= (int)(BTD + STATE)) ? (out + BTD) : p_stfb;
    scan3_kernel<<<2 * Bb * Hh, 256>>>(p_proj, p_w, p_proj + BTD, p_proj + 2 * BTD,
                                       init_state, u, p_y, st_out);

    // ---- gate (needs g) + output projection
    cudaStreamWaitEvent(0, eG, 0);
    gn_gate_kernel<<<(Bb * Tt * Hh) / 8, 256>>>(p_y, p_proj + 3 * BTD, ln_w, ln_b, p_opre);
    gemm_h<0><<<dim3(8, 32, 1), 256, GSMEM>>>(
        p_opre, 0, 1024, p_W5 + 4ll * 1024 * 1024, 0, 1024, out, 0, 1024,
        nullptr, 0, nullptr, nullptr, 1024);
}